// round 1
// baseline (speedup 1.0000x reference)
#include <cuda_runtime.h>

#define NN 10000
#define EE 160000
#define CC 128
#define DD 512
#define HH 64
#define W4C 640
#define HS 66   // padded stride for transposed h tiles in smem

#define INV_SQRT3 0.57735026918962576f
#define INV_SQRT2 0.70710678118654752f
#define LIN_SCALE 0.088388347648318447f   // 1/sqrt(128)

// Scratch (device globals: no runtime allocation allowed)
__device__ float g_w[(size_t)EE * W4C];    // radial weights [E,5,128]
__device__ float g_agg[(size_t)NN * DD];   // segment-sum accumulator

typedef unsigned long long u64;

__device__ __forceinline__ u64 pack2(float lo, float hi) {
    u64 r; asm("mov.b64 %0, {%1, %2};" : "=l"(r) : "f"(lo), "f"(hi)); return r;
}
__device__ __forceinline__ void unpack2(u64 v, float& lo, float& hi) {
    asm("mov.b64 {%0, %1}, %2;" : "=f"(lo), "=f"(hi) : "l"(v));
}
__device__ __forceinline__ void fma2(u64& d, u64 a, u64 b) {
    asm("fma.rn.f32x2 %0, %1, %2, %0;" : "+l"(d) : "l"(a), "l"(b));
}
__device__ __forceinline__ float silu_f(float x) {
    return x / (1.0f + __expf(-x));
}

// One 64x64 MLP layer with silu. h tiles are stored TRANSPOSED in smem:
// sIn[k*HS + e] so that edge-pairs load as 8-byte LDS -> packed f32x2 operand.
__device__ __forceinline__ void layer64(const float* __restrict__ W,
                                        const float* sIn, float* sOut,
                                        int j, int eg)
{
    u64 acc[8];
#pragma unroll
    for (int i = 0; i < 8; ++i) acc[i] = 0ull;
#pragma unroll 2
    for (int k = 0; k < HH; ++k) {
        float wv = __ldg(W + k * HH + j);      // L1-resident (16 KB)
        u64 wv2 = pack2(wv, wv);
        const u64* hp = (const u64*)(sIn + k * HS + eg * 16);
#pragma unroll
        for (int i = 0; i < 8; ++i) fma2(acc[i], hp[i], wv2);
    }
#pragma unroll
    for (int i = 0; i < 8; ++i) {
        float lo, hi; unpack2(acc[i], lo, hi);
        sOut[j * HS + eg * 16 + 2 * i]     = silu_f(lo);
        sOut[j * HS + eg * 16 + 2 * i + 1] = silu_f(hi);
    }
}

// Kernel 1: radial MLP -> g_w. 64 edges per block, 256 threads.
__global__ void __launch_bounds__(256)
mlp_kernel(const float* __restrict__ emb, const float* __restrict__ Wm1,
           const float* __restrict__ Wm2, const float* __restrict__ Wm3,
           const float* __restrict__ Wm4)
{
    __shared__ __align__(16) float sW1[8 * HH];
    __shared__ __align__(16) float sE[64 * 8];
    __shared__ __align__(16) float sHa[HH * HS];
    __shared__ __align__(16) float sHb[HH * HS];

    const int t = threadIdx.x;
    const size_t e0 = (size_t)blockIdx.x * 64;

    for (int i = t; i < 512; i += 256) { sW1[i] = Wm1[i]; sE[i] = emb[e0 * 8 + i]; }
    __syncthreads();

    const int j  = t & 63;   // feature/output column
    const int eg = t >> 6;   // edge-group (16 edges each)

    // layer 1: [64,8] @ [8,64] -> silu -> transposed sHa[j][e]
#pragma unroll
    for (int ee = 0; ee < 16; ++ee) {
        const int e = eg * 16 + ee;
        float acc = 0.f;
#pragma unroll
        for (int r = 0; r < 8; ++r) acc += sE[e * 8 + r] * sW1[r * HH + j];
        sHa[j * HS + e] = silu_f(acc);
    }
    __syncthreads();
    layer64(Wm2, sHa, sHb, j, eg);
    __syncthreads();
    layer64(Wm3, sHb, sHa, j, eg);
    __syncthreads();

    // GEMM4: [64,64] @ [64,640] -> g_w
    for (int pass = 0; pass < 10; ++pass) {
        const int col = pass * 64 + j;
        u64 acc[8];
#pragma unroll
        for (int i = 0; i < 8; ++i) acc[i] = 0ull;
#pragma unroll 2
        for (int k = 0; k < HH; ++k) {
            float wv = __ldg(Wm4 + k * W4C + col);  // coalesced, L1/L2-resident
            u64 wv2 = pack2(wv, wv);
            const u64* hp = (const u64*)(sHa + k * HS + eg * 16);
#pragma unroll
            for (int i = 0; i < 8; ++i) fma2(acc[i], hp[i], wv2);
        }
#pragma unroll
        for (int i = 0; i < 8; ++i) {
            float lo, hi; unpack2(acc[i], lo, hi);
            g_w[(e0 + eg * 16 + 2 * i)     * W4C + col] = lo;
            g_w[(e0 + eg * 16 + 2 * i + 1) * W4C + col] = hi;
        }
    }
}

// Kernel 2: zero the aggregation buffer (d_out-independent scratch init)
__global__ void __launch_bounds__(256)
zero_kernel()
{
    const size_t i = (size_t)blockIdx.x * 256 + threadIdx.x;
    g_agg[i] = 0.f;
}

// Kernel 3: per-edge tensor-product messages + atomic scatter into g_agg.
// One warp per edge; each lane owns 4 channels.
__global__ void __launch_bounds__(256)
msg_kernel(const float* __restrict__ nf, const float* __restrict__ ef,
           const float* __restrict__ attrs,
           const int* __restrict__ snd, const int* __restrict__ rcv)
{
    const size_t e = (size_t)((blockIdx.x * 256 + threadIdx.x) >> 5);
    const int lane = threadIdx.x & 31;

    const int s = snd[e], r = rcv[e];
    const float4 sh = *(const float4*)(attrs + e * 4);
    const float sh0 = sh.x, s1x = sh.y, s1y = sh.z, s1z = sh.w;

    const float* ps = nf + (size_t)s * DD;
    const float* pr = nf + (size_t)r * DD;
    const float* pe = ef + e * DD;
    const int c0 = lane * 4;

    float x0[4];
    {
        float4 a = *(const float4*)(ps + c0);
        float4 b = *(const float4*)(pr + c0);
        float4 c = *(const float4*)(pe + c0);
        x0[0] = a.x + b.x + c.x; x0[1] = a.y + b.y + c.y;
        x0[2] = a.z + b.z + c.z; x0[3] = a.w + b.w + c.w;
    }
    float xv[12];
#pragma unroll
    for (int q = 0; q < 3; ++q) {
        const int off = CC + 3 * c0 + 4 * q;
        float4 a = *(const float4*)(ps + off);
        float4 b = *(const float4*)(pr + off);
        float4 c = *(const float4*)(pe + off);
        xv[4 * q + 0] = a.x + b.x + c.x; xv[4 * q + 1] = a.y + b.y + c.y;
        xv[4 * q + 2] = a.z + b.z + c.z; xv[4 * q + 3] = a.w + b.w + c.w;
    }

    const float* pw = g_w + e * W4C + c0;
    float w0[4], w1[4], w2[4], w3[4], w4[4];
    { float4 v = *(const float4*)(pw      ); w0[0]=v.x; w0[1]=v.y; w0[2]=v.z; w0[3]=v.w; }
    { float4 v = *(const float4*)(pw + 128); w1[0]=v.x; w1[1]=v.y; w1[2]=v.z; w1[3]=v.w; }
    { float4 v = *(const float4*)(pw + 256); w2[0]=v.x; w2[1]=v.y; w2[2]=v.z; w2[3]=v.w; }
    { float4 v = *(const float4*)(pw + 384); w3[0]=v.x; w3[1]=v.y; w3[2]=v.z; w3[3]=v.w; }
    { float4 v = *(const float4*)(pw + 512); w4[0]=v.x; w4[1]=v.y; w4[2]=v.z; w4[3]=v.w; }

    float* pagg = g_agg + (size_t)r * DD;
#pragma unroll
    for (int cc = 0; cc < 4; ++cc) {
        const float u0 = xv[3 * cc], u1 = xv[3 * cc + 1], u2 = xv[3 * cc + 2];
        const float dot = u0 * s1x + u1 * s1y + u2 * s1z;
        const float m0 = w0[cc] * x0[cc] * sh0 + w1[cc] * dot * INV_SQRT3;
        const float cx = u1 * s1z - u2 * s1y;
        const float cy = u2 * s1x - u0 * s1z;
        const float cz = u0 * s1y - u1 * s1x;
        const float m1x = w2[cc] * u0 * sh0 + w3[cc] * x0[cc] * s1x + w4[cc] * cx * INV_SQRT2;
        const float m1y = w2[cc] * u1 * sh0 + w3[cc] * x0[cc] * s1y + w4[cc] * cy * INV_SQRT2;
        const float m1z = w2[cc] * u2 * sh0 + w3[cc] * x0[cc] * s1z + w4[cc] * cz * INV_SQRT2;
        atomicAdd(pagg + c0 + cc, m0);
        atomicAdd(pagg + CC + 3 * (c0 + cc) + 0, m1x);
        atomicAdd(pagg + CC + 3 * (c0 + cc) + 1, m1y);
        atomicAdd(pagg + CC + 3 * (c0 + cc) + 2, m1z);
    }
}

// Kernel 4: out = agg + eq_linear(agg, res) + eq_linear(nf, skip).
// 8 nodes per block; thread (d, g) accumulates 4 nodes x {scalar, x, y, z}.
__global__ void __launch_bounds__(256)
out_kernel(const float* __restrict__ nf,
           const float* __restrict__ rW0, const float* __restrict__ rW1,
           const float* __restrict__ sW0, const float* __restrict__ sW1,
           float* __restrict__ out)
{
    __shared__ float sA[8 * DD];
    __shared__ float sN[8 * DD];
    const int t = threadIdx.x;
    const size_t n0 = (size_t)blockIdx.x * 8;

    for (int i = t; i < 8 * DD; i += 256) {
        sA[i] = g_agg[n0 * DD + i];
        sN[i] = nf[n0 * DD + i];
    }
    __syncthreads();

    const int d = t & 127;
    const int g = t >> 7;

    float a0[4] = {0, 0, 0, 0};
    float ax[4] = {0, 0, 0, 0};
    float ay[4] = {0, 0, 0, 0};
    float az[4] = {0, 0, 0, 0};

    for (int c = 0; c < CC; ++c) {
        const float wr0 = __ldg(rW0 + c * CC + d);
        const float ws0 = __ldg(sW0 + c * CC + d);
        const float wr1 = __ldg(rW1 + c * CC + d);
        const float ws1 = __ldg(sW1 + c * CC + d);
#pragma unroll
        for (int nn = 0; nn < 4; ++nn) {
            const float* A  = sA + (g * 4 + nn) * DD;
            const float* Nf = sN + (g * 4 + nn) * DD;
            a0[nn] += A[c] * wr0 + Nf[c] * ws0;
            ax[nn] += A[CC + 3 * c + 0] * wr1 + Nf[CC + 3 * c + 0] * ws1;
            ay[nn] += A[CC + 3 * c + 1] * wr1 + Nf[CC + 3 * c + 1] * ws1;
            az[nn] += A[CC + 3 * c + 2] * wr1 + Nf[CC + 3 * c + 2] * ws1;
        }
    }
#pragma unroll
    for (int nn = 0; nn < 4; ++nn) {
        const int n = g * 4 + nn;
        const size_t ob = (n0 + n) * DD;
        const float* A = sA + n * DD;
        out[ob + d] = A[d] + a0[nn] * LIN_SCALE;
        out[ob + CC + 3 * d + 0] = A[CC + 3 * d + 0] + ax[nn] * LIN_SCALE;
        out[ob + CC + 3 * d + 1] = A[CC + 3 * d + 1] + ay[nn] * LIN_SCALE;
        out[ob + CC + 3 * d + 2] = A[CC + 3 * d + 2] + az[nn] * LIN_SCALE;
    }
}

extern "C" void kernel_launch(void* const* d_in, const int* in_sizes, int n_in,
                              void* d_out, int out_size)
{
    const float* nf    = (const float*)d_in[0];
    const float* ef    = (const float*)d_in[1];
    const float* attrs = (const float*)d_in[2];
    const float* emb   = (const float*)d_in[3];
    const int*   snd   = (const int*)d_in[4];
    const int*   rcv   = (const int*)d_in[5];
    const float* Wm1   = (const float*)d_in[6];
    const float* Wm2   = (const float*)d_in[7];
    const float* Wm3   = (const float*)d_in[8];
    const float* Wm4   = (const float*)d_in[9];
    const float* rW0   = (const float*)d_in[10];
    const float* rW1   = (const float*)d_in[11];
    const float* sW0   = (const float*)d_in[12];
    const float* sW1   = (const float*)d_in[13];
    float* out = (float*)d_out;

    zero_kernel<<<(NN * DD) / 256, 256>>>();                       // 20000 blocks
    mlp_kernel<<<EE / 64, 256>>>(emb, Wm1, Wm2, Wm3, Wm4);         // 2500 blocks
    msg_kernel<<<EE / 8, 256>>>(nf, ef, attrs, snd, rcv);          // 20000 blocks
    out_kernel<<<NN / 8, 256>>>(nf, rW0, rW1, sW0, sW1, out);      // 1250 blocks
}

// round 3
// speedup vs baseline: 2.0319x; 2.0319x over previous
#include <cuda_runtime.h>
#include <cstdint>

#define NN 10000
#define EE 160000
#define CC 128
#define DD 512
#define HH 64
#define W4C 640
#define HT 130   // padded stride for transposed h tiles [k][e], 128 edges + 2 pad

#define INV_SQRT3 0.57735026918962576f
#define INV_SQRT2 0.70710678118654752f
#define LIN_SCALE 0.088388347648318447f   // 1/sqrt(128)

// Scratch (device globals: no runtime allocation allowed)
__device__ float g_w[(size_t)EE * W4C];    // radial weights [E,640]
__device__ float g_agg[(size_t)NN * DD];   // segment-sum accumulator

typedef unsigned long long u64;

__device__ __forceinline__ u64 pack2(float lo, float hi) {
    u64 r; asm("mov.b64 %0, {%1, %2};" : "=l"(r) : "f"(lo), "f"(hi)); return r;
}
__device__ __forceinline__ void unpack2(u64 v, float& lo, float& hi) {
    asm("mov.b64 {%0, %1}, %2;" : "=f"(lo), "=f"(hi) : "l"(v));
}
__device__ __forceinline__ void fma2(u64& d, u64 a, u64 b) {
    asm("fma.rn.f32x2 %0, %1, %2, %0;" : "+l"(d) : "l"(a), "l"(b));
}
__device__ __forceinline__ float silu_f(float x) { return x / (1.0f + __expf(-x)); }

// ---------------------------------------------------------------------------
// One 64->64 layer, register-blocked: this thread computes 4 columns
// (jbase..jbase+3) for 8 edges (ebase..ebase+7). Input/output transposed
// [k][e] with stride HT. Weights streamed via LDG.128 (L1/L2 resident).
// ---------------------------------------------------------------------------
__device__ __forceinline__ void layer_rb(const float* __restrict__ W,
                                         const float* sIn, float* sOut,
                                         int jbase, int ebase)
{
    u64 acc[4][4];
#pragma unroll
    for (int c = 0; c < 4; ++c)
#pragma unroll
        for (int p = 0; p < 4; ++p) acc[c][p] = 0ull;

#pragma unroll 4
    for (int k = 0; k < HH; ++k) {
        const float4 w4 = __ldg((const float4*)(W + k * HH + jbase));
        const u64* hp = (const u64*)(sIn + k * HT + ebase);
        const u64 h0 = hp[0], h1 = hp[1], h2 = hp[2], h3 = hp[3];
        const float wv[4] = {w4.x, w4.y, w4.z, w4.w};
#pragma unroll
        for (int c = 0; c < 4; ++c) {
            const u64 w2 = pack2(wv[c], wv[c]);
            fma2(acc[c][0], h0, w2);
            fma2(acc[c][1], h1, w2);
            fma2(acc[c][2], h2, w2);
            fma2(acc[c][3], h3, w2);
        }
    }
#pragma unroll
    for (int c = 0; c < 4; ++c) {
        u64* op = (u64*)(sOut + (jbase + c) * HT + ebase);
#pragma unroll
        for (int p = 0; p < 4; ++p) {
            float lo, hi; unpack2(acc[c][p], lo, hi);
            op[p] = pack2(silu_f(lo), silu_f(hi));
        }
    }
}

// One 64-column pass of the [128e,64] @ [64,640] GEMM, same blocking, no silu,
// stores float4 rows straight to g_w.
__device__ __forceinline__ void gemm4_pass(const float* __restrict__ Wm4,
                                           const float* sIn,
                                           int col0, int jbase, int ebase, size_t e0)
{
    u64 acc[4][4];
#pragma unroll
    for (int c = 0; c < 4; ++c)
#pragma unroll
        for (int p = 0; p < 4; ++p) acc[c][p] = 0ull;

#pragma unroll 4
    for (int k = 0; k < HH; ++k) {
        const float4 w4 = __ldg((const float4*)(Wm4 + k * W4C + col0 + jbase));
        const u64* hp = (const u64*)(sIn + k * HT + ebase);
        const u64 h0 = hp[0], h1 = hp[1], h2 = hp[2], h3 = hp[3];
        const float wv[4] = {w4.x, w4.y, w4.z, w4.w};
#pragma unroll
        for (int c = 0; c < 4; ++c) {
            const u64 w2 = pack2(wv[c], wv[c]);
            fma2(acc[c][0], h0, w2);
            fma2(acc[c][1], h1, w2);
            fma2(acc[c][2], h2, w2);
            fma2(acc[c][3], h3, w2);
        }
    }
#pragma unroll
    for (int p = 0; p < 4; ++p) {
        float v0[4], v1[4];
#pragma unroll
        for (int c = 0; c < 4; ++c) unpack2(acc[c][p], v0[c], v1[c]);
        float* d0 = g_w + (e0 + (size_t)(ebase + 2 * p)) * W4C + col0 + jbase;
        float* d1 = d0 + W4C;
        *(float4*)d0 = make_float4(v0[0], v0[1], v0[2], v0[3]);
        *(float4*)d1 = make_float4(v1[0], v1[1], v1[2], v1[3]);
    }
}

// ---------------------------------------------------------------------------
// Kernel 1: full radial MLP for 128 edges per block, 256 threads.
// dyn smem: sE[1024] | sW1[512] | sHa[64*130] | sHb[64*130]  = 72704 B
// ---------------------------------------------------------------------------
__global__ void __launch_bounds__(256, 3)
mlp_kernel(const float* __restrict__ emb, const float* __restrict__ Wm1,
           const float* __restrict__ Wm2, const float* __restrict__ Wm3,
           const float* __restrict__ Wm4)
{
    extern __shared__ float sm[];
    float* sE  = sm;            // 128 edges x 8
    float* sW1 = sm + 1024;     // 8 x 64
    float* sHa = sm + 1536;     // [64][130]
    float* sHb = sm + 1536 + HH * HT;

    const int tid = threadIdx.x;
    const size_t e0 = (size_t)blockIdx.x * 128;

    for (int i = tid; i < 1024; i += 256) sE[i] = emb[e0 * 8 + i];
    for (int i = tid; i < 512; i += 256)  sW1[i] = Wm1[i];
    __syncthreads();

    const int jq = tid & 15;          // 16 col-groups of 4 cols
    const int eg = tid >> 4;          // 16 edge-groups of 8 edges
    const int jbase = jq * 4;
    const int ebase = eg * 8;

    // layer 1: [128,8] @ [8,64] -> silu -> transposed sHa
    {
        float w[8][4];
#pragma unroll
        for (int r = 0; r < 8; ++r) {
            const float4 w4 = *(const float4*)(sW1 + r * HH + jbase);
            w[r][0] = w4.x; w[r][1] = w4.y; w[r][2] = w4.z; w[r][3] = w4.w;
        }
#pragma unroll
        for (int e = 0; e < 8; ++e) {
            const float4 ea = *(const float4*)(sE + (ebase + e) * 8);
            const float4 eb = *(const float4*)(sE + (ebase + e) * 8 + 4);
            const float er[8] = {ea.x, ea.y, ea.z, ea.w, eb.x, eb.y, eb.z, eb.w};
#pragma unroll
            for (int c = 0; c < 4; ++c) {
                float acc = 0.f;
#pragma unroll
                for (int r = 0; r < 8; ++r) acc += er[r] * w[r][c];
                sHa[(jbase + c) * HT + ebase + e] = silu_f(acc);
            }
        }
    }
    __syncthreads();
    layer_rb(Wm2, sHa, sHb, jbase, ebase);
    __syncthreads();
    layer_rb(Wm3, sHb, sHa, jbase, ebase);
    __syncthreads();

#pragma unroll 1
    for (int pass = 0; pass < 10; ++pass)
        gemm4_pass(Wm4, sHa, pass * 64, jbase, ebase, e0);
}

// ---------------------------------------------------------------------------
// Kernel 2: zero the aggregation buffer (float4)
// ---------------------------------------------------------------------------
__global__ void __launch_bounds__(256)
zero_kernel()
{
    const size_t i = (size_t)blockIdx.x * 256 + threadIdx.x;
    ((float4*)g_agg)[i] = make_float4(0.f, 0.f, 0.f, 0.f);
}

// ---------------------------------------------------------------------------
// Kernel 3: per-edge tensor-product messages + vector red scatter.
// One warp per edge; each lane owns 4 channels.
// ---------------------------------------------------------------------------
__global__ void __launch_bounds__(256)
msg_kernel(const float* __restrict__ nf, const float* __restrict__ ef,
           const float* __restrict__ attrs,
           const int* __restrict__ snd, const int* __restrict__ rcv)
{
    const size_t e = (size_t)((blockIdx.x * 256 + threadIdx.x) >> 5);
    const int lane = threadIdx.x & 31;

    const int s = snd[e], r = rcv[e];
    const float4 sh = *(const float4*)(attrs + e * 4);
    const float sh0 = sh.x, s1x = sh.y, s1y = sh.z, s1z = sh.w;

    const float* ps = nf + (size_t)s * DD;
    const float* pr = nf + (size_t)r * DD;
    const float* pe = ef + e * DD;
    const int c0 = lane * 4;

    float x0[4];
    {
        float4 a = *(const float4*)(ps + c0);
        float4 b = *(const float4*)(pr + c0);
        float4 c = *(const float4*)(pe + c0);
        x0[0] = a.x + b.x + c.x; x0[1] = a.y + b.y + c.y;
        x0[2] = a.z + b.z + c.z; x0[3] = a.w + b.w + c.w;
    }
    float xv[12];
#pragma unroll
    for (int q = 0; q < 3; ++q) {
        const int off = CC + 3 * c0 + 4 * q;
        float4 a = *(const float4*)(ps + off);
        float4 b = *(const float4*)(pr + off);
        float4 c = *(const float4*)(pe + off);
        xv[4 * q + 0] = a.x + b.x + c.x; xv[4 * q + 1] = a.y + b.y + c.y;
        xv[4 * q + 2] = a.z + b.z + c.z; xv[4 * q + 3] = a.w + b.w + c.w;
    }

    const float* pw = g_w + e * W4C + c0;
    float w0[4], w1[4], w2[4], w3[4], w4[4];
    { float4 v = *(const float4*)(pw      ); w0[0]=v.x; w0[1]=v.y; w0[2]=v.z; w0[3]=v.w; }
    { float4 v = *(const float4*)(pw + 128); w1[0]=v.x; w1[1]=v.y; w1[2]=v.z; w1[3]=v.w; }
    { float4 v = *(const float4*)(pw + 256); w2[0]=v.x; w2[1]=v.y; w2[2]=v.z; w2[3]=v.w; }
    { float4 v = *(const float4*)(pw + 384); w3[0]=v.x; w3[1]=v.y; w3[2]=v.z; w3[3]=v.w; }
    { float4 v = *(const float4*)(pw + 512); w4[0]=v.x; w4[1]=v.y; w4[2]=v.z; w4[3]=v.w; }

    float m0v[4], m1v[12];
#pragma unroll
    for (int cc = 0; cc < 4; ++cc) {
        const float u0 = xv[3 * cc], u1 = xv[3 * cc + 1], u2 = xv[3 * cc + 2];
        const float dot = u0 * s1x + u1 * s1y + u2 * s1z;
        m0v[cc] = w0[cc] * x0[cc] * sh0 + w1[cc] * dot * INV_SQRT3;
        const float cx = u1 * s1z - u2 * s1y;
        const float cy = u2 * s1x - u0 * s1z;
        const float cz = u0 * s1y - u1 * s1x;
        m1v[3 * cc + 0] = w2[cc] * u0 * sh0 + w3[cc] * x0[cc] * s1x + w4[cc] * cx * INV_SQRT2;
        m1v[3 * cc + 1] = w2[cc] * u1 * sh0 + w3[cc] * x0[cc] * s1y + w4[cc] * cy * INV_SQRT2;
        m1v[3 * cc + 2] = w2[cc] * u2 * sh0 + w3[cc] * x0[cc] * s1z + w4[cc] * cz * INV_SQRT2;
    }

    float* pagg = g_agg + (size_t)r * DD;
    asm volatile("red.global.add.v4.f32 [%0], {%1,%2,%3,%4};"
                 :: "l"(pagg + c0), "f"(m0v[0]), "f"(m0v[1]), "f"(m0v[2]), "f"(m0v[3])
                 : "memory");
    float* pv = pagg + CC + 3 * c0;
    asm volatile("red.global.add.v4.f32 [%0], {%1,%2,%3,%4};"
                 :: "l"(pv), "f"(m1v[0]), "f"(m1v[1]), "f"(m1v[2]), "f"(m1v[3])
                 : "memory");
    asm volatile("red.global.add.v4.f32 [%0], {%1,%2,%3,%4};"
                 :: "l"(pv + 4), "f"(m1v[4]), "f"(m1v[5]), "f"(m1v[6]), "f"(m1v[7])
                 : "memory");
    asm volatile("red.global.add.v4.f32 [%0], {%1,%2,%3,%4};"
                 :: "l"(pv + 8), "f"(m1v[8]), "f"(m1v[9]), "f"(m1v[10]), "f"(m1v[11])
                 : "memory");
}

// ---------------------------------------------------------------------------
// Kernel 4: out = agg + eq_linear(agg,res) + eq_linear(nf,skip).
// 16 nodes/block, 256 threads. Thread = (d-group of 4, node-pair of 2).
// Acts staged in SoA smem [c][node] (stride OST); node-pair packed f32x2.
// dyn smem: 8 arrays x 128 x 18 floats = 73728 B
// ---------------------------------------------------------------------------
#define OST 18
#define OARR (CC * OST)

__global__ void __launch_bounds__(256, 2)
out_kernel(const float* __restrict__ nf,
           const float* __restrict__ rW0, const float* __restrict__ rW1,
           const float* __restrict__ skW0, const float* __restrict__ skW1,
           float* __restrict__ out)
{
    extern __shared__ float osm[];
    float* sA0 = osm;               // +ax*OARR for Ax/Ay/Az
    float* sN0 = osm + 4 * OARR;    // +ax*OARR for Nx/Ny/Nz

    const int tid = threadIdx.x;
    const size_t n0 = (size_t)blockIdx.x * 16;

    for (int i = tid; i < 16 * DD; i += 256) {
        const int n = i >> 9;
        const int q = i & 511;
        const float va = g_agg[(n0 + n) * DD + q];
        const float vb = nf[(n0 + n) * DD + q];
        if (q < CC) {
            sA0[q * OST + n] = va;
            sN0[q * OST + n] = vb;
        } else {
            const int rr = q - CC;
            const int c = rr / 3;
            const int ax = rr - 3 * c;
            sA0[(1 + ax) * OARR + c * OST + n] = va;
            sN0[(1 + ax) * OARR + c * OST + n] = vb;
        }
    }
    __syncthreads();

    const int dg = tid & 31;
    const int ng = tid >> 5;
    const int d0 = dg * 4;
    const int nn2 = ng * 2;

    u64 acc0[4], accx[4], accy[4], accz[4];
#pragma unroll
    for (int d = 0; d < 4; ++d) { acc0[d] = 0ull; accx[d] = 0ull; accy[d] = 0ull; accz[d] = 0ull; }

#pragma unroll 4
    for (int c = 0; c < CC; ++c) {
        const float4 wr0 = __ldg((const float4*)(rW0  + c * CC + d0));
        const float4 ws0 = __ldg((const float4*)(skW0 + c * CC + d0));
        const float4 wr1 = __ldg((const float4*)(rW1  + c * CC + d0));
        const float4 ws1 = __ldg((const float4*)(skW1 + c * CC + d0));
        const int ab = c * OST + nn2;
        const u64 pA0 = *(const u64*)(sA0 + ab);
        const u64 pAx = *(const u64*)(sA0 + OARR + ab);
        const u64 pAy = *(const u64*)(sA0 + 2 * OARR + ab);
        const u64 pAz = *(const u64*)(sA0 + 3 * OARR + ab);
        const u64 pN0 = *(const u64*)(sN0 + ab);
        const u64 pNx = *(const u64*)(sN0 + OARR + ab);
        const u64 pNy = *(const u64*)(sN0 + 2 * OARR + ab);
        const u64 pNz = *(const u64*)(sN0 + 3 * OARR + ab);

        const float r0a[4] = {wr0.x, wr0.y, wr0.z, wr0.w};
        const float s0a[4] = {ws0.x, ws0.y, ws0.z, ws0.w};
        const float r1a[4] = {wr1.x, wr1.y, wr1.z, wr1.w};
        const float s1a[4] = {ws1.x, ws1.y, ws1.z, ws1.w};
#pragma unroll
        for (int d = 0; d < 4; ++d) {
            const u64 pr0 = pack2(r0a[d], r0a[d]);
            const u64 ps0 = pack2(s0a[d], s0a[d]);
            const u64 pr1 = pack2(r1a[d], r1a[d]);
            const u64 ps1 = pack2(s1a[d], s1a[d]);
            fma2(acc0[d], pA0, pr0); fma2(acc0[d], pN0, ps0);
            fma2(accx[d], pAx, pr1); fma2(accx[d], pNx, ps1);
            fma2(accy[d], pAy, pr1); fma2(accy[d], pNy, ps1);
            fma2(accz[d], pAz, pr1); fma2(accz[d], pNz, ps1);
        }
    }

#pragma unroll
    for (int s = 0; s < 2; ++s) {
        const int n = nn2 + s;
        const size_t ob = (n0 + n) * DD;
        float o4[4], vv[12];
#pragma unroll
        for (int d = 0; d < 4; ++d) {
            float lo, hi, v;
            unpack2(acc0[d], lo, hi); v = s ? hi : lo;
            o4[d] = sA0[(d0 + d) * OST + n] + v * LIN_SCALE;
            unpack2(accx[d], lo, hi); v = s ? hi : lo;
            vv[3 * d + 0] = sA0[OARR + (d0 + d) * OST + n] + v * LIN_SCALE;
            unpack2(accy[d], lo, hi); v = s ? hi : lo;
            vv[3 * d + 1] = sA0[2 * OARR + (d0 + d) * OST + n] + v * LIN_SCALE;
            unpack2(accz[d], lo, hi); v = s ? hi : lo;
            vv[3 * d + 2] = sA0[3 * OARR + (d0 + d) * OST + n] + v * LIN_SCALE;
        }
        *(float4*)(out + ob + d0) = make_float4(o4[0], o4[1], o4[2], o4[3]);
        float* vb = out + ob + CC + 3 * d0;
        *(float4*)(vb    ) = make_float4(vv[0], vv[1], vv[2],  vv[3]);
        *(float4*)(vb + 4) = make_float4(vv[4], vv[5], vv[6],  vv[7]);
        *(float4*)(vb + 8) = make_float4(vv[8], vv[9], vv[10], vv[11]);
    }
}

// ---------------------------------------------------------------------------
extern "C" void kernel_launch(void* const* d_in, const int* in_sizes, int n_in,
                              void* d_out, int out_size)
{
    const float* nf    = (const float*)d_in[0];
    const float* ef    = (const float*)d_in[1];
    const float* attrs = (const float*)d_in[2];
    const float* emb   = (const float*)d_in[3];
    const int*   snd   = (const int*)d_in[4];
    const int*   rcv   = (const int*)d_in[5];
    const float* Wm1   = (const float*)d_in[6];
    const float* Wm2   = (const float*)d_in[7];
    const float* Wm3   = (const float*)d_in[8];
    const float* Wm4   = (const float*)d_in[9];
    const float* rW0   = (const float*)d_in[10];
    const float* rW1   = (const float*)d_in[11];
    const float* sW0   = (const float*)d_in[12];
    const float* sW1   = (const float*)d_in[13];
    float* out = (float*)d_out;

    const int mlp_smem = (1536 + 2 * HH * HT) * 4;   // 72704 B
    const int out_smem = 8 * OARR * 4;               // 73728 B
    static bool attr_done = false;
    if (!attr_done) {
        cudaFuncSetAttribute(mlp_kernel, cudaFuncAttributeMaxDynamicSharedMemorySize, mlp_smem);
        cudaFuncSetAttribute(out_kernel, cudaFuncAttributeMaxDynamicSharedMemorySize, out_smem);
        attr_done = true;
    }

    zero_kernel<<<(NN * DD) / (256 * 4), 256>>>();
    mlp_kernel<<<EE / 128, 256, mlp_smem>>>(emb, Wm1, Wm2, Wm3, Wm4);
    msg_kernel<<<EE / 8, 256>>>(nf, ef, attrs, snd, rcv);
    out_kernel<<<NN / 16, 256, out_smem>>>(nf, rW0, rW1, sW0, sW1, out);
}